// round 6
// baseline (speedup 1.0000x reference)
#include <cuda_runtime.h>

#define N_NODES 100000
#define N_EDGES 800000
#define NF 64
#define NH 16
#define NG 64

// ---------------- device scratch (no allocations allowed) ----------------
// 16-byte alignment REQUIRED: accessed via float4 and red.global.add.v4.f32.
__device__ __align__(16) float g_y1[N_NODES * NH];      // x @ W1_rel
__device__ __align__(16) float g_root1[N_NODES * NH];   // x @ W1_root + b1
__device__ __align__(16) float g_agg1[N_NODES * NH];    // edge-aggregated y1
__device__ __align__(16) float g_t[N_NODES];            // h1 . w2r
__device__ __align__(16) float g_rpart[N_NODES];        // h1 . w2o + b2.Wlin
__device__ __align__(16) float g_aggS[N_NODES];         // edge-aggregated t
__device__ float g_gsum[NG];
__device__ int   g_gcnt[NG];
__device__ float g_w2r[NH];
__device__ float g_w2o[NH];
__device__ float g_c;
__device__ int   g_is64;   // 1 if edge_index/batch are int64, 0 if int32

// ---------------- dtype detection ----------------
// Node ids < 2^31, so if data is int64 every high 32-bit word is zero.
// If data is int32, odd words are random node ids in [0,100000) -> ~never all 0.
__global__ void k_detect(const unsigned int* __restrict__ w) {
    __shared__ int any;
    if (threadIdx.x == 0) any = 0;
    __syncthreads();
    if (w[threadIdx.x * 2 + 1] != 0u) atomicOr(&any, 1);
    __syncthreads();
    if (threadIdx.x == 0) g_is64 = any ? 0 : 1;
}

__device__ __forceinline__ int idx_at(const void* p, long long pos, int is64) {
    if (is64) return (int)((const long long*)p)[pos];
    return ((const int*)p)[pos];
}

// ---------------- kernels ----------------

__global__ void k_zero() {
    int i = blockIdx.x * blockDim.x + threadIdx.x;
    if (i < N_NODES * NH) g_agg1[i] = 0.f;
    if (i < N_NODES)      g_aggS[i] = 0.f;
    if (i < NG)           { g_gsum[i] = 0.f; g_gcnt[i] = 0; }
}

// Fold layer-2 weights through the final linear:
//   w2r = W2_rel @ Wlin, w2o = W2_root @ Wlin, c = b2 . Wlin
__global__ void k_pre(const float* __restrict__ W2_rel,
                      const float* __restrict__ W2_root,
                      const float* __restrict__ b2,
                      const float* __restrict__ Wlin) {
    int h = threadIdx.x;
    if (h < NH) {
        float a = 0.f, b = 0.f;
        #pragma unroll
        for (int j = 0; j < NH; j++) {
            float wl = Wlin[j];
            a += W2_rel [h * NH + j] * wl;
            b += W2_root[h * NH + j] * wl;
        }
        g_w2r[h] = a;
        g_w2o[h] = b;
    }
    if (h == 0) {
        float c = 0.f;
        #pragma unroll
        for (int j = 0; j < NH; j++) c += b2[j] * Wlin[j];
        g_c = c;
    }
}

// Per-node GEMM: y1 = x @ W1_rel ; root1 = x @ W1_root + b1
__global__ __launch_bounds__(256) void k_node1(
    const float* __restrict__ x,
    const float* __restrict__ W1_rel,
    const float* __restrict__ W1_root,
    const float* __restrict__ b1) {

    __shared__ float sWr[NF * NH];
    __shared__ float sWo[NF * NH];
    __shared__ float sb[NH];
    for (int i = threadIdx.x; i < NF * NH; i += blockDim.x) {
        sWr[i] = W1_rel[i];
        sWo[i] = W1_root[i];
    }
    if (threadIdx.x < NH) sb[threadIdx.x] = b1[threadIdx.x];
    __syncthreads();

    int node = blockIdx.x * blockDim.x + threadIdx.x;
    if (node >= N_NODES) return;

    float accR[NH], accO[NH];
    #pragma unroll
    for (int h = 0; h < NH; h++) { accR[h] = 0.f; accO[h] = 0.f; }

    const float4* xr = reinterpret_cast<const float4*>(x + (size_t)node * NF);
    #pragma unroll 4
    for (int kk = 0; kk < NF / 4; kk++) {
        float4 xv = xr[kk];
        float xs[4] = {xv.x, xv.y, xv.z, xv.w};
        #pragma unroll
        for (int c = 0; c < 4; c++) {
            int k = kk * 4 + c;
            float v = xs[c];
            const float* wr = &sWr[k * NH];
            const float* wo = &sWo[k * NH];
            #pragma unroll
            for (int h = 0; h < NH; h++) {
                accR[h] += v * wr[h];
                accO[h] += v * wo[h];
            }
        }
    }

    float4* yp = reinterpret_cast<float4*>(g_y1    + (size_t)node * NH);
    float4* rp = reinterpret_cast<float4*>(g_root1 + (size_t)node * NH);
    #pragma unroll
    for (int q = 0; q < 4; q++) {
        float4 a, b;
        a.x = accR[q*4+0]; a.y = accR[q*4+1]; a.z = accR[q*4+2]; a.w = accR[q*4+3];
        b.x = accO[q*4+0] + sb[q*4+0];
        b.y = accO[q*4+1] + sb[q*4+1];
        b.z = accO[q*4+2] + sb[q*4+2];
        b.w = accO[q*4+3] + sb[q*4+3];
        yp[q] = a;
        rp[q] = b;
    }
}

__device__ __forceinline__ void red_add_v4(float* p, float4 v) {
    asm volatile("red.global.add.v4.f32 [%0], {%1,%2,%3,%4};"
                 :: "l"(p), "f"(v.x), "f"(v.y), "f"(v.z), "f"(v.w)
                 : "memory");
}

// Edge pass 1: agg1[dst] += y1[src]  (16 floats via 4 x red.v4)
__global__ __launch_bounds__(256) void k_edge1(const void* __restrict__ ei) {
    int e = blockIdx.x * blockDim.x + threadIdx.x;
    if (e >= N_EDGES) return;
    int is64 = g_is64;
    int s = idx_at(ei, e, is64);
    int d = idx_at(ei, (long long)N_EDGES + e, is64);
    const float4* y = reinterpret_cast<const float4*>(g_y1 + (size_t)s * NH);
    float4 v0 = y[0], v1 = y[1], v2 = y[2], v3 = y[3];
    float* a = g_agg1 + (size_t)d * NH;
    red_add_v4(a,      v0);
    red_add_v4(a + 4,  v1);
    red_add_v4(a + 8,  v2);
    red_add_v4(a + 12, v3);
}

// Per-node: h1 = relu(agg1 + root1); t = h1.w2r; rpart = h1.w2o + c
__global__ __launch_bounds__(256) void k_node2() {
    __shared__ float swr[NH], swo[NH];
    __shared__ float sc;
    if (threadIdx.x < NH) { swr[threadIdx.x] = g_w2r[threadIdx.x]; swo[threadIdx.x] = g_w2o[threadIdx.x]; }
    if (threadIdx.x == 0) sc = g_c;
    __syncthreads();

    int node = blockIdx.x * blockDim.x + threadIdx.x;
    if (node >= N_NODES) return;

    const float4* ap = reinterpret_cast<const float4*>(g_agg1  + (size_t)node * NH);
    const float4* rp = reinterpret_cast<const float4*>(g_root1 + (size_t)node * NH);
    float t = 0.f, r = 0.f;
    #pragma unroll
    for (int q = 0; q < 4; q++) {
        float4 a = ap[q], b = rp[q];
        float h0 = fmaxf(a.x + b.x, 0.f);
        float h1 = fmaxf(a.y + b.y, 0.f);
        float h2 = fmaxf(a.z + b.z, 0.f);
        float h3 = fmaxf(a.w + b.w, 0.f);
        t += h0 * swr[q*4+0] + h1 * swr[q*4+1] + h2 * swr[q*4+2] + h3 * swr[q*4+3];
        r += h0 * swo[q*4+0] + h1 * swo[q*4+1] + h2 * swo[q*4+2] + h3 * swo[q*4+3];
    }
    g_t[node] = t;
    g_rpart[node] = r + sc;
}

// Edge pass 2: aggS[dst] += t[src]  (scalar RED)
__global__ __launch_bounds__(256) void k_edge2(const void* __restrict__ ei) {
    int e = blockIdx.x * blockDim.x + threadIdx.x;
    if (e >= N_EDGES) return;
    int is64 = g_is64;
    int s = idx_at(ei, e, is64);
    int d = idx_at(ei, (long long)N_EDGES + e, is64);
    atomicAdd(g_aggS + d, g_t[s]);  // result unused -> REDG
}

// Pool: per-graph sum of s[i] = aggS[i] + rpart[i], plus node counts.
__global__ __launch_bounds__(256) void k_pool(const void* __restrict__ batch) {
    __shared__ float gs[NG];
    __shared__ int   gc[NG];
    if (threadIdx.x < NG) { gs[threadIdx.x] = 0.f; gc[threadIdx.x] = 0; }
    __syncthreads();

    int node = blockIdx.x * blockDim.x + threadIdx.x;
    int is64 = g_is64;
    if (node < N_NODES) {
        float s = g_aggS[node] + g_rpart[node];
        int b = idx_at(batch, node, is64);
        atomicAdd(&gs[b], s);
        atomicAdd(&gc[b], 1);
    }
    __syncthreads();
    if (threadIdx.x < NG && gc[threadIdx.x] > 0) {
        atomicAdd(&g_gsum[threadIdx.x], gs[threadIdx.x]);
        atomicAdd(&g_gcnt[threadIdx.x], gc[threadIdx.x]);
    }
}

__global__ void k_out(float* __restrict__ out, const float* __restrict__ blin) {
    int g = threadIdx.x;
    if (g < NG) {
        float cnt = (float)g_gcnt[g];
        out[g] = g_gsum[g] / fmaxf(cnt, 1.f) + blin[0];
    }
}

// ---------------- launch ----------------
extern "C" void kernel_launch(void* const* d_in, const int* in_sizes, int n_in,
                              void* d_out, int out_size) {
    const float* x       = (const float*)d_in[0];
    const void*  ei      = d_in[1];
    const void*  batch   = d_in[2];
    const float* W1_rel  = (const float*)d_in[3];
    const float* W1_root = (const float*)d_in[4];
    const float* b1      = (const float*)d_in[5];
    const float* W2_rel  = (const float*)d_in[6];
    const float* W2_root = (const float*)d_in[7];
    const float* b2      = (const float*)d_in[8];
    const float* Wlin    = (const float*)d_in[9];
    const float* blin    = (const float*)d_in[10];
    float*       out     = (float*)d_out;

    (void)in_sizes; (void)n_in; (void)out_size;

    k_detect<<<1, 1024>>>((const unsigned int*)ei);
    k_zero  <<<(N_NODES * NH + 255) / 256, 256>>>();
    k_pre   <<<1, 32>>>(W2_rel, W2_root, b2, Wlin);
    k_node1 <<<(N_NODES + 255) / 256, 256>>>(x, W1_rel, W1_root, b1);
    k_edge1 <<<(N_EDGES + 255) / 256, 256>>>(ei);
    k_node2 <<<(N_NODES + 255) / 256, 256>>>();
    k_edge2 <<<(N_EDGES + 255) / 256, 256>>>(ei);
    k_pool  <<<(N_NODES + 255) / 256, 256>>>(batch);
    k_out   <<<1, 64>>>(out, blin);
}

// round 7
// speedup vs baseline: 1.0234x; 1.0234x over previous
#include <cuda_runtime.h>

#define N_NODES 100000
#define N_EDGES 800000
#define NF 64
#define NH 16
#define NG 64

// ---------------- device scratch (no allocations allowed) ----------------
__device__ __align__(16) float g_y1[N_NODES * NH];      // x @ W1_rel
__device__ __align__(16) float g_root1[N_NODES * NH];   // x @ W1_root + b1
__device__ __align__(16) float g_agg1[N_NODES * NH];    // edge-aggregated y1
__device__ __align__(16) float g_t[N_NODES];            // h1 . w2r
__device__ __align__(16) float g_rpart[N_NODES];        // h1 . w2o + b2.Wlin
__device__ __align__(16) float g_aggS[N_NODES];         // edge-aggregated t
__device__ float    g_gsum[NG];
__device__ int      g_gcnt[NG];
__device__ float    g_w2r[NH];
__device__ float    g_w2o[NH];
__device__ float    g_c;
__device__ int      g_is64;
__device__ unsigned g_ticket;

__device__ __forceinline__ int idx_at(const void* p, long long pos, int is64) {
    if (is64) return (int)((const long long*)p)[pos];
    return ((const int*)p)[pos];
}

// ---------------- init: zero scratch + dtype detect + layer-2 fold ----------------
__global__ void k_init(const unsigned int* __restrict__ eiw,
                       const float* __restrict__ W2_rel,
                       const float* __restrict__ W2_root,
                       const float* __restrict__ b2,
                       const float* __restrict__ Wlin) {
    int i = blockIdx.x * blockDim.x + threadIdx.x;
    if (i < N_NODES * NH) g_agg1[i] = 0.f;
    if (i < N_NODES)      g_aggS[i] = 0.f;
    if (i < NG)           { g_gsum[i] = 0.f; g_gcnt[i] = 0; }
    if (i == 0)           g_ticket = 0u;

    if (blockIdx.x == 0) {
        // dtype detection: node ids < 2^31, so int64 data has all-zero high words.
        __shared__ int any;
        if (threadIdx.x == 0) any = 0;
        __syncthreads();
        int nz = 0;
        #pragma unroll
        for (int q = 0; q < 4; q++)
            if (eiw[(threadIdx.x * 4 + q) * 2 + 1] != 0u) nz = 1;
        if (nz) atomicOr(&any, 1);
        __syncthreads();
        if (threadIdx.x == 0) g_is64 = any ? 0 : 1;
    } else if (blockIdx.x == 1) {
        // fold layer-2 weights through final linear
        int h = threadIdx.x;
        if (h < NH) {
            float a = 0.f, b = 0.f;
            #pragma unroll
            for (int j = 0; j < NH; j++) {
                float wl = Wlin[j];
                a += W2_rel [h * NH + j] * wl;
                b += W2_root[h * NH + j] * wl;
            }
            g_w2r[h] = a;
            g_w2o[h] = b;
        }
        if (h == 0) {
            float c = 0.f;
            #pragma unroll
            for (int j = 0; j < NH; j++) c += b2[j] * Wlin[j];
            g_c = c;
        }
    }
}

// ---------------- node GEMM: 2 nodes per thread (weights LDS amortized) ----------------
__global__ __launch_bounds__(256) void k_node1(
    const float* __restrict__ x,
    const float* __restrict__ W1_rel,
    const float* __restrict__ W1_root,
    const float* __restrict__ b1) {

    __shared__ float sWr[NF * NH];
    __shared__ float sWo[NF * NH];
    __shared__ float sb[NH];
    for (int i = threadIdx.x; i < NF * NH; i += 256) {
        sWr[i] = W1_rel[i];
        sWo[i] = W1_root[i];
    }
    if (threadIdx.x < NH) sb[threadIdx.x] = b1[threadIdx.x];
    __syncthreads();

    int n0 = blockIdx.x * 512 + threadIdx.x;
    int n1 = n0 + 256;
    bool v0 = n0 < N_NODES, v1 = n1 < N_NODES;
    int m0 = v0 ? n0 : 0, m1 = v1 ? n1 : 0;

    float aR0[NH], aO0[NH], aR1[NH], aO1[NH];
    #pragma unroll
    for (int h = 0; h < NH; h++) { aR0[h]=0.f; aO0[h]=0.f; aR1[h]=0.f; aO1[h]=0.f; }

    const float4* x0 = reinterpret_cast<const float4*>(x + (size_t)m0 * NF);
    const float4* x1 = reinterpret_cast<const float4*>(x + (size_t)m1 * NF);

    #pragma unroll 2
    for (int kk = 0; kk < NF / 4; kk++) {
        float4 a4 = x0[kk];
        float4 b4 = x1[kk];
        float as[4] = {a4.x, a4.y, a4.z, a4.w};
        float bs[4] = {b4.x, b4.y, b4.z, b4.w};
        #pragma unroll
        for (int c = 0; c < 4; c++) {
            int k = kk * 4 + c;
            const float* wr = &sWr[k * NH];
            const float* wo = &sWo[k * NH];
            float va = as[c], vb = bs[c];
            #pragma unroll
            for (int h = 0; h < NH; h++) {
                float w1 = wr[h], w2 = wo[h];
                aR0[h] += va * w1;
                aO0[h] += va * w2;
                aR1[h] += vb * w1;
                aO1[h] += vb * w2;
            }
        }
    }

    if (v0) {
        float4* yp = reinterpret_cast<float4*>(g_y1    + (size_t)n0 * NH);
        float4* rp = reinterpret_cast<float4*>(g_root1 + (size_t)n0 * NH);
        #pragma unroll
        for (int q = 0; q < 4; q++) {
            float4 a, b;
            a.x = aR0[q*4+0]; a.y = aR0[q*4+1]; a.z = aR0[q*4+2]; a.w = aR0[q*4+3];
            b.x = aO0[q*4+0] + sb[q*4+0];
            b.y = aO0[q*4+1] + sb[q*4+1];
            b.z = aO0[q*4+2] + sb[q*4+2];
            b.w = aO0[q*4+3] + sb[q*4+3];
            yp[q] = a; rp[q] = b;
        }
    }
    if (v1) {
        float4* yp = reinterpret_cast<float4*>(g_y1    + (size_t)n1 * NH);
        float4* rp = reinterpret_cast<float4*>(g_root1 + (size_t)n1 * NH);
        #pragma unroll
        for (int q = 0; q < 4; q++) {
            float4 a, b;
            a.x = aR1[q*4+0]; a.y = aR1[q*4+1]; a.z = aR1[q*4+2]; a.w = aR1[q*4+3];
            b.x = aO1[q*4+0] + sb[q*4+0];
            b.y = aO1[q*4+1] + sb[q*4+1];
            b.z = aO1[q*4+2] + sb[q*4+2];
            b.w = aO1[q*4+3] + sb[q*4+3];
            yp[q] = a; rp[q] = b;
        }
    }
}

__device__ __forceinline__ void red_add_v4(float* p, float4 v) {
    asm volatile("red.global.add.v4.f32 [%0], {%1,%2,%3,%4};"
                 :: "l"(p), "f"(v.x), "f"(v.y), "f"(v.z), "f"(v.w)
                 : "memory");
}

// Edge pass 1: agg1[dst] += y1[src]; 2 edges/thread, loads front-batched for MLP.
__global__ __launch_bounds__(256) void k_edge1(const void* __restrict__ ei) {
    int e0 = blockIdx.x * 512 + threadIdx.x;
    int e1 = e0 + 256;
    int is64 = g_is64;
    bool p0 = e0 < N_EDGES, p1 = e1 < N_EDGES;
    int f0 = p0 ? e0 : 0, f1 = p1 ? e1 : 0;

    int s0 = idx_at(ei, f0, is64);
    int s1 = idx_at(ei, f1, is64);
    int d0 = idx_at(ei, (long long)N_EDGES + f0, is64);
    int d1 = idx_at(ei, (long long)N_EDGES + f1, is64);

    const float4* y0 = reinterpret_cast<const float4*>(g_y1 + (size_t)s0 * NH);
    const float4* y1 = reinterpret_cast<const float4*>(g_y1 + (size_t)s1 * NH);
    float4 a0 = y0[0], a1 = y0[1], a2 = y0[2], a3 = y0[3];
    float4 b0 = y1[0], b1 = y1[1], b2 = y1[2], b3 = y1[3];

    if (p0) {
        float* a = g_agg1 + (size_t)d0 * NH;
        red_add_v4(a,      a0);
        red_add_v4(a + 4,  a1);
        red_add_v4(a + 8,  a2);
        red_add_v4(a + 12, a3);
    }
    if (p1) {
        float* a = g_agg1 + (size_t)d1 * NH;
        red_add_v4(a,      b0);
        red_add_v4(a + 4,  b1);
        red_add_v4(a + 8,  b2);
        red_add_v4(a + 12, b3);
    }
}

// Per-node: h1 = relu(agg1 + root1); t = h1.w2r; rpart = h1.w2o + c
__global__ __launch_bounds__(256) void k_node2() {
    __shared__ float swr[NH], swo[NH];
    __shared__ float sc;
    if (threadIdx.x < NH) { swr[threadIdx.x] = g_w2r[threadIdx.x]; swo[threadIdx.x] = g_w2o[threadIdx.x]; }
    if (threadIdx.x == 0) sc = g_c;
    __syncthreads();

    int node = blockIdx.x * blockDim.x + threadIdx.x;
    if (node >= N_NODES) return;

    const float4* ap = reinterpret_cast<const float4*>(g_agg1  + (size_t)node * NH);
    const float4* rp = reinterpret_cast<const float4*>(g_root1 + (size_t)node * NH);
    float t = 0.f, r = 0.f;
    #pragma unroll
    for (int q = 0; q < 4; q++) {
        float4 a = ap[q], b = rp[q];
        float h0 = fmaxf(a.x + b.x, 0.f);
        float h1 = fmaxf(a.y + b.y, 0.f);
        float h2 = fmaxf(a.z + b.z, 0.f);
        float h3 = fmaxf(a.w + b.w, 0.f);
        t += h0 * swr[q*4+0] + h1 * swr[q*4+1] + h2 * swr[q*4+2] + h3 * swr[q*4+3];
        r += h0 * swo[q*4+0] + h1 * swo[q*4+1] + h2 * swo[q*4+2] + h3 * swo[q*4+3];
    }
    g_t[node] = t;
    g_rpart[node] = r + sc;
}

// Edge pass 2: aggS[dst] += t[src]; 2 edges/thread.
__global__ __launch_bounds__(256) void k_edge2(const void* __restrict__ ei) {
    int e0 = blockIdx.x * 512 + threadIdx.x;
    int e1 = e0 + 256;
    int is64 = g_is64;
    bool p0 = e0 < N_EDGES, p1 = e1 < N_EDGES;
    int f0 = p0 ? e0 : 0, f1 = p1 ? e1 : 0;

    int s0 = idx_at(ei, f0, is64);
    int s1 = idx_at(ei, f1, is64);
    int d0 = idx_at(ei, (long long)N_EDGES + f0, is64);
    int d1 = idx_at(ei, (long long)N_EDGES + f1, is64);
    float t0 = g_t[s0];
    float t1 = g_t[s1];

    if (p0) atomicAdd(g_aggS + d0, t0);
    if (p1) atomicAdd(g_aggS + d1, t1);
}

// Pool + output (last block writes out after global reduction completes).
__global__ __launch_bounds__(256) void k_pool(const void* __restrict__ batch,
                                              float* __restrict__ out,
                                              const float* __restrict__ blin) {
    __shared__ float gs[NG];
    __shared__ int   gc[NG];
    if (threadIdx.x < NG) { gs[threadIdx.x] = 0.f; gc[threadIdx.x] = 0; }
    __syncthreads();

    int node = blockIdx.x * blockDim.x + threadIdx.x;
    int is64 = g_is64;
    if (node < N_NODES) {
        float s = g_aggS[node] + g_rpart[node];
        int b = idx_at(batch, node, is64);
        atomicAdd(&gs[b], s);
        atomicAdd(&gc[b], 1);
    }
    __syncthreads();
    if (threadIdx.x < NG && gc[threadIdx.x] > 0) {
        atomicAdd(&g_gsum[threadIdx.x], gs[threadIdx.x]);
        atomicAdd(&g_gcnt[threadIdx.x], gc[threadIdx.x]);
    }

    __threadfence();
    __shared__ bool last;
    if (threadIdx.x == 0) {
        unsigned old = atomicAdd(&g_ticket, 1u);
        last = (old == gridDim.x - 1);
    }
    __syncthreads();
    if (last && threadIdx.x < NG) {
        float cnt = (float)g_gcnt[threadIdx.x];
        out[threadIdx.x] = g_gsum[threadIdx.x] / fmaxf(cnt, 1.f) + blin[0];
    }
}

// ---------------- launch ----------------
extern "C" void kernel_launch(void* const* d_in, const int* in_sizes, int n_in,
                              void* d_out, int out_size) {
    const float* x       = (const float*)d_in[0];
    const void*  ei      = d_in[1];
    const void*  batch   = d_in[2];
    const float* W1_rel  = (const float*)d_in[3];
    const float* W1_root = (const float*)d_in[4];
    const float* b1      = (const float*)d_in[5];
    const float* W2_rel  = (const float*)d_in[6];
    const float* W2_root = (const float*)d_in[7];
    const float* b2      = (const float*)d_in[8];
    const float* Wlin    = (const float*)d_in[9];
    const float* blin    = (const float*)d_in[10];
    float*       out     = (float*)d_out;

    (void)in_sizes; (void)n_in; (void)out_size;

    k_init <<<(N_NODES * NH + 255) / 256, 256>>>((const unsigned int*)ei,
                                                 W2_rel, W2_root, b2, Wlin);
    k_node1<<<(N_NODES + 511) / 512, 256>>>(x, W1_rel, W1_root, b1);
    k_edge1<<<(N_EDGES + 511) / 512, 256>>>(ei);
    k_node2<<<(N_NODES + 255) / 256, 256>>>();
    k_edge2<<<(N_EDGES + 511) / 512, 256>>>(ei);
    k_pool <<<(N_NODES + 255) / 256, 256>>>(batch, out, blin);
}